// round 2
// baseline (speedup 1.0000x reference)
#include <cuda_runtime.h>
#include <math.h>

// Problem constants
#define BATCH 16
#define CDIM  64
#define HW    4096            // H*W
#define NROWS 65536           // BATCH*HW
#define KCODE 512
#define TPB   256
#define NBLK  (NROWS / TPB)   // 256 CTAs

// d_out layout (float32): out[4194304] | commit | perp | active | indices[65536]
#define OUT_ELEMS   (BATCH * CDIM * HW)   // 4194304
#define COMMIT_OFF  OUT_ELEMS
#define PERP_OFF    (OUT_ELEMS + 1)
#define ACT_OFF     (OUT_ELEMS + 2)
#define IDX_OFF     (OUT_ELEMS + 3)

// Scratch (no allocations allowed -> device globals)
__device__ float g_e2[KCODE];
__device__ int   g_hist[KCODE];
__device__ float g_partial[NBLK];

// ---------------------------------------------------------------------------
// Kernel 1: codebook squared norms + zero histogram
// ---------------------------------------------------------------------------
__global__ void vq_prep(const float* __restrict__ emb) {
    int k = blockIdx.x * blockDim.x + threadIdx.x;
    if (k < KCODE) {
        const float4* e4 = (const float4*)(emb + k * CDIM);
        float s = 0.f;
        #pragma unroll
        for (int j = 0; j < CDIM / 4; j++) {
            float4 e = e4[j];
            s += e.x * e.x + e.y * e.y + e.z * e.z + e.w * e.w;
        }
        g_e2[k]   = s;
        g_hist[k] = 0;
    }
}

// ---------------------------------------------------------------------------
// Kernel 2: fused distance-GEMM + argmin + gather + histogram + partial sums
// Dynamic smem: codebook [KCODE*CDIM] + e2 [KCODE]  (~130 KB)
// ---------------------------------------------------------------------------
extern __shared__ float s_mem[];

__global__ __launch_bounds__(TPB, 1)
void vq_main(const float* __restrict__ in,
             const float* __restrict__ emb,
             float* __restrict__ out) {
    float* Es  = s_mem;                 // [KCODE * CDIM]
    float* e2s = s_mem + KCODE * CDIM;  // [KCODE]

    __shared__ int   s_hist[KCODE];
    __shared__ float s_red[TPB / 32];

    // Cooperative codebook load (L2-resident source, 128 KB)
    {
        float4*       dst = (float4*)Es;
        const float4* src = (const float4*)emb;
        #pragma unroll 4
        for (int i = threadIdx.x; i < KCODE * CDIM / 4; i += TPB) dst[i] = src[i];
        for (int i = threadIdx.x; i < KCODE; i += TPB) e2s[i] = g_e2[i];
        for (int i = threadIdx.x; i < KCODE; i += TPB) s_hist[i] = 0;
    }
    __syncthreads();

    const int n  = blockIdx.x * TPB + threadIdx.x;  // row id
    const int b  = n >> 12;                          // n / 4096
    const int hw = n & 4095;

    // Load x row (strided BCHW channel reads, coalesced across lanes), track x^2
    const float* xin = in + (size_t)b * CDIM * HW + hw;
    float x[CDIM];
    float x2 = 0.f;
    #pragma unroll
    for (int c = 0; c < CDIM; c++) {
        x[c] = xin[(size_t)c * HW];
        x2  += x[c] * x[c];
    }

    // argmin_k  e2[k] - 2 * dot(x, e_k)   (warp-broadcast smem reads)
    float best = 3.402823e38f;
    int   bidx = 0;
    #pragma unroll 2
    for (int k = 0; k < KCODE; k++) {
        const float4* e4 = (const float4*)(Es + k * CDIM);
        float d0 = 0.f, d1 = 0.f, d2 = 0.f, d3 = 0.f;
        #pragma unroll
        for (int j = 0; j < CDIM / 4; j++) {
            float4 e = e4[j];
            d0 += x[4 * j + 0] * e.x;
            d1 += x[4 * j + 1] * e.y;
            d2 += x[4 * j + 2] * e.z;
            d3 += x[4 * j + 3] * e.w;
        }
        float d = e2s[k] - 2.f * ((d0 + d1) + (d2 + d3));
        if (d < best) { best = d; bidx = k; }
    }

    // Histogram (int atomics -> deterministic)
    atomicAdd(&s_hist[bidx], 1);

    // indices as float (exact for k < 2^24)
    out[IDX_OFF + n] = (float)bidx;

    // quantized output = emb[idx], scattered back to BCHW
    {
        float*       op = out + (size_t)b * CDIM * HW + hw;
        const float* eb = Es + bidx * CDIM;
        #pragma unroll
        for (int c = 0; c < CDIM; c++) op[(size_t)c * HW] = eb[c];
    }

    // per-row distance = x2 + best ; block-reduce deterministically
    float dsum = x2 + best;
    #pragma unroll
    for (int off = 16; off > 0; off >>= 1)
        dsum += __shfl_down_sync(0xFFFFFFFFu, dsum, off);
    if ((threadIdx.x & 31) == 0) s_red[threadIdx.x >> 5] = dsum;
    __syncthreads();
    if (threadIdx.x == 0) {
        float t = 0.f;
        #pragma unroll
        for (int w = 0; w < TPB / 32; w++) t += s_red[w];
        g_partial[blockIdx.x] = t;
    }

    // flush histogram to global (deterministic int adds)
    __syncthreads();
    for (int i = threadIdx.x; i < KCODE; i += TPB) {
        int h = s_hist[i];
        if (h) atomicAdd(&g_hist[i], h);
    }
}

// ---------------------------------------------------------------------------
// Kernel 3: finalize scalars (perplexity, commitment, active_codes)
// ---------------------------------------------------------------------------
__global__ void vq_finalize(const float* __restrict__ weight,
                            float* __restrict__ out) {
    __shared__ float red[KCODE];
    const int t = threadIdx.x;  // 512 threads

    // entropy term
    float p    = (float)g_hist[t] * (1.0f / (float)NROWS);
    float term = p * logf(p + 1e-10f);
    red[t] = term;
    __syncthreads();
    #pragma unroll
    for (int s = KCODE / 2; s > 0; s >>= 1) {
        if (t < s) red[t] += red[t + s];
        __syncthreads();
    }
    float ent = red[0];
    __syncthreads();

    // commitment sum over per-CTA partials
    red[t] = (t < NBLK) ? g_partial[t] : 0.f;
    __syncthreads();
    #pragma unroll
    for (int s = KCODE / 2; s > 0; s >>= 1) {
        if (t < s) red[t] += red[t + s];
        __syncthreads();
    }
    float csum = red[0];
    __syncthreads();

    // active codes
    red[t] = (weight[t] >= 0.01f) ? 1.f : 0.f;
    __syncthreads();
    #pragma unroll
    for (int s = KCODE / 2; s > 0; s >>= 1) {
        if (t < s) red[t] += red[t + s];
        __syncthreads();
    }

    if (t == 0) {
        out[COMMIT_OFF] = csum * (1.0f / (float)OUT_ELEMS);
        out[PERP_OFF]   = expf(-ent);
        out[ACT_OFF]    = red[0];
    }
}

// ---------------------------------------------------------------------------
extern "C" void kernel_launch(void* const* d_in, const int* in_sizes, int n_in,
                              void* d_out, int out_size) {
    const float* in     = (const float*)d_in[0];  // inputs     [16,64,64,64]
    const float* emb    = (const float*)d_in[1];  // emb_weight [512,64]
    const float* weight = (const float*)d_in[2];  // weight     [512]
    float*       out    = (float*)d_out;

    const size_t smem = (size_t)(KCODE * CDIM + KCODE) * sizeof(float);
    cudaFuncSetAttribute(vq_main, cudaFuncAttributeMaxDynamicSharedMemorySize,
                         (int)smem);

    vq_prep<<<2, 256>>>(emb);
    vq_main<<<NBLK, TPB, smem>>>(in, emb, out);
    vq_finalize<<<1, KCODE>>>(weight, out);
}

// round 9
// speedup vs baseline: 1.7900x; 1.7900x over previous
#include <cuda_runtime.h>
#include <math.h>
#include <stdint.h>

// ---------------------------------------------------------------------------
// Problem constants
// ---------------------------------------------------------------------------
#define BATCH 16
#define CDIM  64
#define HW    4096
#define NROWS 65536           // BATCH*HW
#define KCODE 512
#define TPB   256             // rows per CTA (8 warps x 32 rows)
#define NBLK  (NROWS / TPB)   // 256 CTAs

// d_out layout (float32): out[4194304] | commit | perp | active | indices[65536]
#define OUT_ELEMS   (BATCH * CDIM * HW)
#define COMMIT_OFF  OUT_ELEMS
#define PERP_OFF    (OUT_ELEMS + 1)
#define ACT_OFF     (OUT_ELEMS + 2)
#define IDX_OFF     (OUT_ELEMS + 3)

// Padded smem row stride (floats): bank = (4*row + k) % 32 -> conflict-free
#define XPAD 68

// Scratch (allocations forbidden -> device globals)
__device__ float g_e2[KCODE];
__device__ int   g_hist[KCODE];
__device__ float g_partial[NBLK];

// ---------------------------------------------------------------------------
__device__ __forceinline__ uint32_t tf32_rna(float v) {
    uint32_t r;
    asm("cvt.rna.tf32.f32 %0, %1;" : "=r"(r) : "f"(v));
    return r;
}

// mma.sync m16n8k8 tf32 (portable PTX, fallback HMMA on sm_103)
__device__ __forceinline__ void mma_tf32(float* d, const uint32_t* a,
                                         uint32_t b0, uint32_t b1) {
    asm volatile(
        "mma.sync.aligned.m16n8k8.row.col.f32.tf32.tf32.f32 "
        "{%0,%1,%2,%3}, {%4,%5,%6,%7}, {%8,%9}, {%0,%1,%2,%3};"
        : "+f"(d[0]), "+f"(d[1]), "+f"(d[2]), "+f"(d[3])
        : "r"(a[0]), "r"(a[1]), "r"(a[2]), "r"(a[3]), "r"(b0), "r"(b1));
}

// ---------------------------------------------------------------------------
// Kernel 1: e2 + zero histogram
// ---------------------------------------------------------------------------
__global__ void vq_prep(const float* __restrict__ emb) {
    int k = threadIdx.x;  // 512
    const float4* e4 = (const float4*)(emb + k * CDIM);
    float s = 0.f;
    #pragma unroll
    for (int j = 0; j < CDIM / 4; j++) {
        float4 e = e4[j];
        s += e.x * e.x + e.y * e.y + e.z * e.z + e.w * e.w;
    }
    g_e2[k]   = s;
    g_hist[k] = 0;
}

// ---------------------------------------------------------------------------
// Kernel 2: fused tf32-mma distance GEMM + argmin + epilogue
// ---------------------------------------------------------------------------
// dynamic smem layout (bytes):
#define OFF_XS   0                                   // 256*68*4 = 69632
#define OFF_ES   69632                               // 512*68*4 = 139264
#define OFF_E2   (69632 + 139264)                    // 2048
#define OFF_HIST (OFF_E2 + 2048)                     // 2048
#define OFF_BEST (OFF_HIST + 2048)                   // 1024
#define OFF_BIDX (OFF_BEST + 1024)                   // 1024
#define OFF_RED  (OFF_BIDX + 1024)                   // 32
#define SMEM_BYTES (OFF_RED + 32)

extern __shared__ char s_raw[];

__global__ __launch_bounds__(TPB, 1)
void vq_main(const float* __restrict__ in,
             const float* __restrict__ emb,
             float* __restrict__ out) {
    float* xs     = (float*)(s_raw + OFF_XS);    // [256][68]
    float* Es     = (float*)(s_raw + OFF_ES);    // [512][68]
    float* e2s    = (float*)(s_raw + OFF_E2);
    int*   s_hist = (int*)(s_raw + OFF_HIST);
    float* s_best = (float*)(s_raw + OFF_BEST);  // [256]
    int*   s_bidx = (int*)(s_raw + OFF_BIDX);    // [256]
    float* s_red  = (float*)(s_raw + OFF_RED);

    const int tid  = threadIdx.x;
    const int wid  = tid >> 5;
    const int lane = tid & 31;
    const int lr   = lane >> 2;   // 0..7
    const int lc   = lane & 3;    // 0..3
    const int mbase = wid * 32;

    const int n  = blockIdx.x * TPB + tid;  // this thread's row
    const int b  = n >> 12;
    const int hw = n & 4095;

    // ---- stage x row (BCHW strided, coalesced across lanes) + x2 ----
    const float* xin = in + (size_t)b * CDIM * HW + hw;
    float x2 = 0.f;
    {
        float xr[CDIM];
        #pragma unroll
        for (int c = 0; c < CDIM; c++) {
            xr[c] = xin[(size_t)c * HW];
            x2 += xr[c] * xr[c];
        }
        float4* xd = (float4*)(xs + tid * XPAD);
        #pragma unroll
        for (int j = 0; j < CDIM / 4; j++)
            xd[j] = make_float4(xr[4*j], xr[4*j+1], xr[4*j+2], xr[4*j+3]);
    }

    // ---- stage codebook + e2 + hist ----
    {
        const float4* src = (const float4*)emb;
        #pragma unroll 4
        for (int i = tid; i < KCODE * CDIM / 4; i += TPB) {
            int code = i >> 4, j = i & 15;           // 16 float4 per code
            *(float4*)(Es + code * XPAD + 4 * j) = src[i];
        }
        for (int i = tid; i < KCODE; i += TPB) { e2s[i] = g_e2[i]; s_hist[i] = 0; }
    }
    __syncthreads();

    // ---- mma GEMM: 64-code chunks, 3 tf32 products ----
    float best[4] = {3.402823e38f, 3.402823e38f, 3.402823e38f, 3.402823e38f};
    int   bidx[4] = {0, 0, 0, 0};

    for (int cb = 0; cb < KCODE; cb += 64) {
        float acc[2][8][4];
        #pragma unroll
        for (int mt = 0; mt < 2; mt++)
            #pragma unroll
            for (int nt = 0; nt < 8; nt++)
                #pragma unroll
                for (int r = 0; r < 4; r++) acc[mt][nt][r] = 0.f;

        #pragma unroll
        for (int ks = 0; ks < 8; ks++) {
            const int k0 = ks * 8;
            // A fragments (hi/lo) for both 16-row tiles
            uint32_t ah[2][4], al[2][4];
            #pragma unroll
            for (int mt = 0; mt < 2; mt++) {
                const int r0 = mbase + mt * 16 + lr;
                float f0 = xs[(r0    ) * XPAD + k0 + lc];
                float f1 = xs[(r0 + 8) * XPAD + k0 + lc];
                float f2 = xs[(r0    ) * XPAD + k0 + lc + 4];
                float f3 = xs[(r0 + 8) * XPAD + k0 + lc + 4];
                ah[mt][0] = tf32_rna(f0); al[mt][0] = tf32_rna(f0 - __uint_as_float(ah[mt][0]));
                ah[mt][1] = tf32_rna(f1); al[mt][1] = tf32_rna(f1 - __uint_as_float(ah[mt][1]));
                ah[mt][2] = tf32_rna(f2); al[mt][2] = tf32_rna(f2 - __uint_as_float(ah[mt][2]));
                ah[mt][3] = tf32_rna(f3); al[mt][3] = tf32_rna(f3 - __uint_as_float(ah[mt][3]));
            }
            #pragma unroll
            for (int nt = 0; nt < 8; nt++) {
                const int code = cb + nt * 8 + lr;
                float bf0 = Es[code * XPAD + k0 + lc];
                float bf1 = Es[code * XPAD + k0 + lc + 4];
                uint32_t bh0 = tf32_rna(bf0);
                uint32_t bh1 = tf32_rna(bf1);
                uint32_t bl0 = tf32_rna(bf0 - __uint_as_float(bh0));
                uint32_t bl1 = tf32_rna(bf1 - __uint_as_float(bh1));
                mma_tf32(acc[0][nt], ah[0], bh0, bh1);   // hi*hi
                mma_tf32(acc[1][nt], ah[1], bh0, bh1);
                mma_tf32(acc[0][nt], ah[0], bl0, bl1);   // hi*lo
                mma_tf32(acc[1][nt], ah[1], bl0, bl1);
                mma_tf32(acc[0][nt], al[0], bh0, bh1);   // lo*hi
                mma_tf32(acc[1][nt], al[1], bh0, bh1);
            }
        }

        // chunk epilogue: d = e2 - 2*dot, running argmin (cols ascending)
        #pragma unroll
        for (int nt = 0; nt < 8; nt++) {
            const int col0 = cb + nt * 8 + lc * 2;
            const float e20 = e2s[col0];
            const float e21 = e2s[col0 + 1];
            #pragma unroll
            for (int mt = 0; mt < 2; mt++) {
                #pragma unroll
                for (int h = 0; h < 2; h++) {     // h=0: row r, h=1: row r+8
                    const int slot = mt * 2 + h;
                    float d0 = fmaf(-2.f, acc[mt][nt][2*h    ], e20);
                    float d1 = fmaf(-2.f, acc[mt][nt][2*h + 1], e21);
                    if (d0 < best[slot]) { best[slot] = d0; bidx[slot] = col0; }
                    if (d1 < best[slot]) { best[slot] = d1; bidx[slot] = col0 + 1; }
                }
            }
        }
    }

    // ---- reduce across the 4 lanes of each row-quad (tie -> lower idx) ----
    #pragma unroll
    for (int s = 0; s < 4; s++) {
        #pragma unroll
        for (int off = 1; off <= 2; off <<= 1) {
            float ov = __shfl_xor_sync(0xFFFFFFFFu, best[s], off);
            int   oi = __shfl_xor_sync(0xFFFFFFFFu, bidx[s], off);
            if (ov < best[s] || (ov == best[s] && oi < bidx[s])) {
                best[s] = ov; bidx[s] = oi;
            }
        }
    }
    if (lc == 0) {
        #pragma unroll
        for (int s = 0; s < 4; s++) {
            const int row = mbase + ((s & 1) << 3) + ((s >> 1) << 4) + lr;
            s_best[row] = best[s];
            s_bidx[row] = bidx[s];
        }
    }
    __syncthreads();

    // ---- per-row epilogue (row = tid) ----
    const int   kbest = s_bidx[tid];
    const float dbest = s_best[tid];

    atomicAdd(&s_hist[kbest], 1);
    out[IDX_OFF + n] = (float)kbest;

    {
        float* op = out + (size_t)b * CDIM * HW + hw;
        const float4* eb = (const float4*)(Es + kbest * XPAD);
        #pragma unroll
        for (int j = 0; j < CDIM / 4; j++) {
            float4 e = eb[j];
            op[(size_t)(4 * j + 0) * HW] = e.x;
            op[(size_t)(4 * j + 1) * HW] = e.y;
            op[(size_t)(4 * j + 2) * HW] = e.z;
            op[(size_t)(4 * j + 3) * HW] = e.w;
        }
    }

    // commitment partial: ||x - e||^2 = x2 + (e2 - 2 dot)
    float dsum = x2 + dbest;
    #pragma unroll
    for (int off = 16; off > 0; off >>= 1)
        dsum += __shfl_down_sync(0xFFFFFFFFu, dsum, off);
    if (lane == 0) s_red[wid] = dsum;
    __syncthreads();
    if (tid == 0) {
        float t = 0.f;
        #pragma unroll
        for (int w = 0; w < TPB / 32; w++) t += s_red[w];
        g_partial[blockIdx.x] = t;
    }
    for (int i = tid; i < KCODE; i += TPB) {
        int h = s_hist[i];
        if (h) atomicAdd(&g_hist[i], h);
    }
}

// ---------------------------------------------------------------------------
// Kernel 3: finalize scalars
// ---------------------------------------------------------------------------
__global__ void vq_finalize(const float* __restrict__ weight,
                            float* __restrict__ out) {
    __shared__ float red[KCODE];
    const int t = threadIdx.x;  // 512

    float p = (float)g_hist[t] * (1.0f / (float)NROWS);
    red[t] = p * logf(p + 1e-10f);
    __syncthreads();
    #pragma unroll
    for (int s = KCODE / 2; s > 0; s >>= 1) {
        if (t < s) red[t] += red[t + s];
        __syncthreads();
    }
    float ent = red[0];
    __syncthreads();

    red[t] = (t < NBLK) ? g_partial[t] : 0.f;
    __syncthreads();
    #pragma unroll
    for (int s = KCODE / 2; s > 0; s >>= 1) {
        if (t < s) red[t] += red[t + s];
        __syncthreads();
    }
    float csum = red[0];
    __syncthreads();

    red[t] = (weight[t] >= 0.01f) ? 1.f : 0.f;
    __syncthreads();
    #pragma unroll
    for (int s = KCODE / 2; s > 0; s >>= 1) {
        if (t < s) red[t] += red[t + s];
        __syncthreads();
    }

    if (t == 0) {
        out[COMMIT_OFF] = csum * (1.0f / (float)OUT_ELEMS);
        out[PERP_OFF]   = expf(-ent);
        out[ACT_OFF]    = red[0];
    }
}

// ---------------------------------------------------------------------------
extern "C" void kernel_launch(void* const* d_in, const int* in_sizes, int n_in,
                              void* d_out, int out_size) {
    const float* in     = (const float*)d_in[0];
    const float* emb    = (const float*)d_in[1];
    const float* weight = (const float*)d_in[2];
    float*       out    = (float*)d_out;

    cudaFuncSetAttribute(vq_main, cudaFuncAttributeMaxDynamicSharedMemorySize,
                         SMEM_BYTES);

    vq_prep<<<1, KCODE>>>(emb);
    vq_main<<<NBLK, TPB, SMEM_BYTES>>>(in, emb, out);
    vq_finalize<<<1, KCODE>>>(weight, out);
}

// round 13
// speedup vs baseline: 1.8595x; 1.0388x over previous
#include <cuda_runtime.h>
#include <math.h>
#include <stdint.h>

// ---------------------------------------------------------------------------
// Problem constants
// ---------------------------------------------------------------------------
#define BATCH 16
#define CDIM  64
#define HW    4096
#define NROWS 65536           // BATCH*HW
#define KCODE 512
#define TPB   256             // rows per CTA (8 warps x 32 rows)
#define NBLK  (NROWS / TPB)   // 256 CTAs

// d_out layout (float32): out[4194304] | commit | perp | active | indices[65536]
#define OUT_ELEMS   (BATCH * CDIM * HW)
#define COMMIT_OFF  OUT_ELEMS
#define PERP_OFF    (OUT_ELEMS + 1)
#define ACT_OFF     (OUT_ELEMS + 2)
#define IDX_OFF     (OUT_ELEMS + 3)

// Padded smem row stride (floats): bank = (4*row + k) % 32 -> conflict-free
#define XPAD 68

// Scratch (allocations forbidden -> device globals; zero-initialized at load,
// and g_hist is re-zeroed at the END of vq_finalize so graph replays always
// start from a clean histogram)
__device__ int   g_hist[KCODE];
__device__ float g_partial[NBLK];

// ---------------------------------------------------------------------------
__device__ __forceinline__ uint32_t tf32_rna(float v) {
    uint32_t r;
    asm("cvt.rna.tf32.f32 %0, %1;" : "=r"(r) : "f"(v));
    return r;
}

// mma.sync m16n8k8 tf32 (portable PTX, fallback HMMA on sm_103)
__device__ __forceinline__ void mma_tf32(float* d, const uint32_t* a,
                                         uint32_t b0, uint32_t b1) {
    asm volatile(
        "mma.sync.aligned.m16n8k8.row.col.f32.tf32.tf32.f32 "
        "{%0,%1,%2,%3}, {%4,%5,%6,%7}, {%8,%9}, {%0,%1,%2,%3};"
        : "+f"(d[0]), "+f"(d[1]), "+f"(d[2]), "+f"(d[3])
        : "r"(a[0]), "r"(a[1]), "r"(a[2]), "r"(a[3]), "r"(b0), "r"(b1));
}

// ---------------------------------------------------------------------------
// Kernel 1: fused tf32-mma distance GEMM + argmin + epilogue
// ---------------------------------------------------------------------------
// dynamic smem layout (bytes):
#define OFF_XS   0                                   // 256*68*4 = 69632
#define OFF_ES   69632                               // 512*68*4 = 139264
#define OFF_E2   (69632 + 139264)                    // 2048
#define OFF_HIST (OFF_E2 + 2048)                     // 2048
#define OFF_BEST (OFF_HIST + 2048)                   // 1024
#define OFF_BIDX (OFF_BEST + 1024)                   // 1024
#define OFF_RED  (OFF_BIDX + 1024)                   // 32
#define SMEM_BYTES (OFF_RED + 32)

extern __shared__ char s_raw[];

__global__ __launch_bounds__(TPB, 1)
void vq_main(const float* __restrict__ in,
             const float* __restrict__ emb,
             float* __restrict__ out) {
    float* xs     = (float*)(s_raw + OFF_XS);    // [256][68]
    float* Es     = (float*)(s_raw + OFF_ES);    // [512][68]
    float* e2s    = (float*)(s_raw + OFF_E2);
    int*   s_hist = (int*)(s_raw + OFF_HIST);
    float* s_best = (float*)(s_raw + OFF_BEST);  // [256]
    int*   s_bidx = (int*)(s_raw + OFF_BIDX);    // [256]
    float* s_red  = (float*)(s_raw + OFF_RED);

    const int tid  = threadIdx.x;
    const int wid  = tid >> 5;
    const int lane = tid & 31;
    const int lr   = lane >> 2;   // 0..7
    const int lc   = lane & 3;    // 0..3
    const int mbase = wid * 32;

    const int n  = blockIdx.x * TPB + tid;  // this thread's row
    const int b  = n >> 12;
    const int hw = n & 4095;

    // ---- stage x row (BCHW strided, coalesced across lanes) + x2 ----
    const float* xin = in + (size_t)b * CDIM * HW + hw;
    float x2 = 0.f;
    {
        float xr[CDIM];
        #pragma unroll
        for (int c = 0; c < CDIM; c++) {
            xr[c] = xin[(size_t)c * HW];
            x2 += xr[c] * xr[c];
        }
        float4* xd = (float4*)(xs + tid * XPAD);
        #pragma unroll
        for (int j = 0; j < CDIM / 4; j++)
            xd[j] = make_float4(xr[4*j], xr[4*j+1], xr[4*j+2], xr[4*j+3]);
    }

    // ---- stage codebook ----
    {
        const float4* src = (const float4*)emb;
        #pragma unroll 4
        for (int i = tid; i < KCODE * CDIM / 4; i += TPB) {
            int code = i >> 4, j = i & 15;           // 16 float4 per code
            *(float4*)(Es + code * XPAD + 4 * j) = src[i];
        }
        for (int i = tid; i < KCODE; i += TPB) s_hist[i] = 0;
    }
    __syncthreads();

    // ---- e2 from staged codebook (replaces the old vq_prep kernel) ----
    #pragma unroll
    for (int i = tid; i < KCODE; i += TPB) {
        const float4* e4 = (const float4*)(Es + i * XPAD);
        float s = 0.f;
        #pragma unroll
        for (int j = 0; j < CDIM / 4; j++) {
            float4 e = e4[j];
            s += e.x * e.x + e.y * e.y + e.z * e.z + e.w * e.w;
        }
        e2s[i] = s;
    }
    __syncthreads();

    // ---- mma GEMM: 64-code chunks, 3 tf32 products, RAW-free schedule ----
    float best[4] = {3.402823e38f, 3.402823e38f, 3.402823e38f, 3.402823e38f};
    int   bidx[4] = {0, 0, 0, 0};

    for (int cb = 0; cb < KCODE; cb += 64) {
        float acc[2][8][4];
        #pragma unroll
        for (int mt = 0; mt < 2; mt++)
            #pragma unroll
            for (int nt = 0; nt < 8; nt++)
                #pragma unroll
                for (int r = 0; r < 4; r++) acc[mt][nt][r] = 0.f;

        #pragma unroll
        for (int ks = 0; ks < 8; ks++) {
            const int k0 = ks * 8;

            // A fragments (hi/lo) for both 16-row tiles
            uint32_t ah[2][4], al[2][4];
            #pragma unroll
            for (int mt = 0; mt < 2; mt++) {
                const int r0 = mbase + mt * 16 + lr;
                float f0 = xs[(r0    ) * XPAD + k0 + lc];
                float f1 = xs[(r0 + 8) * XPAD + k0 + lc];
                float f2 = xs[(r0    ) * XPAD + k0 + lc + 4];
                float f3 = xs[(r0 + 8) * XPAD + k0 + lc + 4];
                ah[mt][0] = tf32_rna(f0); al[mt][0] = tf32_rna(f0 - __uint_as_float(ah[mt][0]));
                ah[mt][1] = tf32_rna(f1); al[mt][1] = tf32_rna(f1 - __uint_as_float(ah[mt][1]));
                ah[mt][2] = tf32_rna(f2); al[mt][2] = tf32_rna(f2 - __uint_as_float(ah[mt][2]));
                ah[mt][3] = tf32_rna(f3); al[mt][3] = tf32_rna(f3 - __uint_as_float(ah[mt][3]));
            }

            // B fragments (hi/lo) for all 8 n-tiles, converted up front
            uint32_t bh[8][2], bl[8][2];
            #pragma unroll
            for (int nt = 0; nt < 8; nt++) {
                const int code = cb + nt * 8 + lr;
                float bf0 = Es[code * XPAD + k0 + lc];
                float bf1 = Es[code * XPAD + k0 + lc + 4];
                bh[nt][0] = tf32_rna(bf0);
                bh[nt][1] = tf32_rna(bf1);
                bl[nt][0] = tf32_rna(bf0 - __uint_as_float(bh[nt][0]));
                bl[nt][1] = tf32_rna(bf1 - __uint_as_float(bh[nt][1]));
            }

            // Three passes over 16 DISTINCT accumulators each ->
            // same-acc reuse distance = 16 MMAs, RAW latency hidden.
            #pragma unroll
            for (int nt = 0; nt < 8; nt++) {           // hi * hi
                mma_tf32(acc[0][nt], ah[0], bh[nt][0], bh[nt][1]);
                mma_tf32(acc[1][nt], ah[1], bh[nt][0], bh[nt][1]);
            }
            #pragma unroll
            for (int nt = 0; nt < 8; nt++) {           // hi * lo
                mma_tf32(acc[0][nt], ah[0], bl[nt][0], bl[nt][1]);
                mma_tf32(acc[1][nt], ah[1], bl[nt][0], bl[nt][1]);
            }
            #pragma unroll
            for (int nt = 0; nt < 8; nt++) {           // lo * hi
                mma_tf32(acc[0][nt], al[0], bh[nt][0], bh[nt][1]);
                mma_tf32(acc[1][nt], al[1], bh[nt][0], bh[nt][1]);
            }
        }

        // chunk epilogue: d = e2 - 2*dot, running argmin (cols ascending)
        #pragma unroll
        for (int nt = 0; nt < 8; nt++) {
            const int col0 = cb + nt * 8 + lc * 2;
            const float e20 = e2s[col0];
            const float e21 = e2s[col0 + 1];
            #pragma unroll
            for (int mt = 0; mt < 2; mt++) {
                #pragma unroll
                for (int h = 0; h < 2; h++) {     // h=0: row r, h=1: row r+8
                    const int slot = mt * 2 + h;
                    float d0 = fmaf(-2.f, acc[mt][nt][2*h    ], e20);
                    float d1 = fmaf(-2.f, acc[mt][nt][2*h + 1], e21);
                    if (d0 < best[slot]) { best[slot] = d0; bidx[slot] = col0; }
                    if (d1 < best[slot]) { best[slot] = d1; bidx[slot] = col0 + 1; }
                }
            }
        }
    }

    // ---- reduce across the 4 lanes of each row-quad (tie -> lower idx) ----
    #pragma unroll
    for (int s = 0; s < 4; s++) {
        #pragma unroll
        for (int off = 1; off <= 2; off <<= 1) {
            float ov = __shfl_xor_sync(0xFFFFFFFFu, best[s], off);
            int   oi = __shfl_xor_sync(0xFFFFFFFFu, bidx[s], off);
            if (ov < best[s] || (ov == best[s] && oi < bidx[s])) {
                best[s] = ov; bidx[s] = oi;
            }
        }
    }
    if (lc == 0) {
        #pragma unroll
        for (int s = 0; s < 4; s++) {
            const int row = mbase + ((s & 1) << 3) + ((s >> 1) << 4) + lr;
            s_best[row] = best[s];
            s_bidx[row] = bidx[s];
        }
    }
    __syncthreads();

    // ---- per-row epilogue (row = tid) ----
    const int   kbest = s_bidx[tid];
    const float dbest = s_best[tid];

    atomicAdd(&s_hist[kbest], 1);
    out[IDX_OFF + n] = (float)kbest;

    {
        float* op = out + (size_t)b * CDIM * HW + hw;
        const float4* eb = (const float4*)(Es + kbest * XPAD);
        #pragma unroll
        for (int j = 0; j < CDIM / 4; j++) {
            float4 e = eb[j];
            op[(size_t)(4 * j + 0) * HW] = e.x;
            op[(size_t)(4 * j + 1) * HW] = e.y;
            op[(size_t)(4 * j + 2) * HW] = e.z;
            op[(size_t)(4 * j + 3) * HW] = e.w;
        }
    }

    // commitment partial: ||x - e||^2 = x2 + (e2 - 2 dot)
    float dsum = x2 + dbest;
    #pragma unroll
    for (int off = 16; off > 0; off >>= 1)
        dsum += __shfl_down_sync(0xFFFFFFFFu, dsum, off);
    if (lane == 0) s_red[wid] = dsum;
    __syncthreads();
    if (tid == 0) {
        float t = 0.f;
        #pragma unroll
        for (int w = 0; w < TPB / 32; w++) t += s_red[w];
        g_partial[blockIdx.x] = t;
    }
    for (int i = tid; i < KCODE; i += TPB) {
        int h = s_hist[i];
        if (h) atomicAdd(&g_hist[i], h);
    }
}

// ---------------------------------------------------------------------------
// Kernel 2: finalize scalars (and re-zero g_hist for the next graph replay)
// ---------------------------------------------------------------------------
__global__ void vq_finalize(const float* __restrict__ weight,
                            float* __restrict__ out) {
    __shared__ float red[KCODE];
    const int t = threadIdx.x;  // 512

    int   hcount = g_hist[t];
    g_hist[t] = 0;               // leave zeroed for next replay
    float p = (float)hcount * (1.0f / (float)NROWS);
    red[t] = p * logf(p + 1e-10f);
    __syncthreads();
    #pragma unroll
    for (int s = KCODE / 2; s > 0; s >>= 1) {
        if (t < s) red[t] += red[t + s];
        __syncthreads();
    }
    float ent = red[0];
    __syncthreads();

    red[t] = (t < NBLK) ? g_partial[t] : 0.f;
    __syncthreads();
    #pragma unroll
    for (int s = KCODE / 2; s > 0; s >>= 1) {
        if (t < s) red[t] += red[t + s];
        __syncthreads();
    }
    float csum = red[0];
    __syncthreads();

    red[t] = (weight[t] >= 0.01f) ? 1.f : 0.f;
    __syncthreads();
    #pragma unroll
    for (int s = KCODE / 2; s > 0; s >>= 1) {
        if (t < s) red[t] += red[t + s];
        __syncthreads();
    }

    if (t == 0) {
        out[COMMIT_OFF] = csum * (1.0f / (float)OUT_ELEMS);
        out[PERP_OFF]   = expf(-ent);
        out[ACT_OFF]    = red[0];
    }
}

// ---------------------------------------------------------------------------
extern "C" void kernel_launch(void* const* d_in, const int* in_sizes, int n_in,
                              void* d_out, int out_size) {
    const float* in     = (const float*)d_in[0];
    const float* emb    = (const float*)d_in[1];
    const float* weight = (const float*)d_in[2];
    float*       out    = (float*)d_out;

    cudaFuncSetAttribute(vq_main, cudaFuncAttributeMaxDynamicSharedMemorySize,
                         SMEM_BYTES);

    vq_main<<<NBLK, TPB, SMEM_BYTES>>>(in, emb, out);
    vq_finalize<<<1, KCODE>>>(weight, out);
}

// round 14
// speedup vs baseline: 1.9577x; 1.0528x over previous
#include <cuda_runtime.h>
#include <cuda_fp16.h>
#include <math.h>
#include <stdint.h>

// ---------------------------------------------------------------------------
// Problem constants
// ---------------------------------------------------------------------------
#define BATCH 16
#define CDIM  64
#define HW    4096
#define NROWS 65536           // BATCH*HW
#define KCODE 512
#define TPB   256             // rows per CTA (8 warps x 32 rows)
#define NBLK  (NROWS / TPB)   // 256 CTAs

// d_out layout (float32): out[4194304] | commit | perp | active | indices[65536]
#define OUT_ELEMS   (BATCH * CDIM * HW)
#define COMMIT_OFF  OUT_ELEMS
#define PERP_OFF    (OUT_ELEMS + 1)
#define ACT_OFF     (OUT_ELEMS + 2)
#define IDX_OFF     (OUT_ELEMS + 3)

// Row layout in smem (uint32 words of half2): 32 hi + 32 lo + 4 pad = 68 words.
// Fragment read bank = (4*row + word) % 32 -> bijective over (lr, lc): no conflicts.
#define WPAD 68

// Scratch (allocations forbidden -> device globals; zero-init at load; g_hist
// re-zeroed at the end of vq_finalize so graph replays start clean)
__device__ int   g_hist[KCODE];
__device__ float g_partial[NBLK];

// ---------------------------------------------------------------------------
// fp16 m16n8k16 mma with fp32 accumulate (portable PTX -> fallback HMMA)
__device__ __forceinline__ void mma_f16(float* d, const uint32_t* a,
                                        uint32_t b0, uint32_t b1) {
    asm volatile(
        "mma.sync.aligned.m16n8k16.row.col.f32.f16.f16.f32 "
        "{%0,%1,%2,%3}, {%4,%5,%6,%7}, {%8,%9}, {%0,%1,%2,%3};"
        : "+f"(d[0]), "+f"(d[1]), "+f"(d[2]), "+f"(d[3])
        : "r"(a[0]), "r"(a[1]), "r"(a[2]), "r"(a[3]), "r"(b0), "r"(b1));
}

__device__ __forceinline__ uint32_t pack_h2(__half lo, __half hi) {
    __half2 h = __halves2half2(lo, hi);   // .x = first k element (low 16 bits)
    return *(uint32_t*)&h;
}

// ---------------------------------------------------------------------------
// dynamic smem layout (bytes):
#define OFF_XS   0                                   // 256*68*4 = 69632
#define OFF_ES   69632                               // 512*68*4 = 139264
#define OFF_E2   (69632 + 139264)                    // 2048
#define OFF_HIST (OFF_E2 + 2048)                     // 2048
#define OFF_BEST (OFF_HIST + 2048)                   // 1024
#define OFF_BIDX (OFF_BEST + 1024)                   // 1024
#define OFF_RED  (OFF_BIDX + 1024)                   // 32
#define SMEM_BYTES (OFF_RED + 32)

extern __shared__ char s_raw[];

__global__ __launch_bounds__(TPB, 1)
void vq_main(const float* __restrict__ in,
             const float* __restrict__ emb,
             float* __restrict__ out) {
    uint32_t* xsu   = (uint32_t*)(s_raw + OFF_XS);   // [256][68] half2 words
    uint32_t* esu   = (uint32_t*)(s_raw + OFF_ES);   // [512][68] half2 words
    float* e2s      = (float*)(s_raw + OFF_E2);
    int*   s_hist   = (int*)(s_raw + OFF_HIST);
    float* s_best   = (float*)(s_raw + OFF_BEST);    // [256]
    int*   s_bidx   = (int*)(s_raw + OFF_BIDX);      // [256]
    float* s_red    = (float*)(s_raw + OFF_RED);

    const int tid  = threadIdx.x;
    const int wid  = tid >> 5;
    const int lane = tid & 31;
    const int lr   = lane >> 2;   // 0..7
    const int lc   = lane & 3;    // 0..3
    const int mbase = wid * 32;

    const int n  = blockIdx.x * TPB + tid;  // this thread's row
    const int b  = n >> 12;
    const int hw = n & 4095;

    // ---- load x row (BCHW strided, coalesced across lanes), x2, split+stage ----
    const float* xin = in + (size_t)b * CDIM * HW + hw;
    float x2 = 0.f;
    {
        float xr[CDIM];
        #pragma unroll
        for (int c = 0; c < CDIM; c++) {
            xr[c] = xin[(size_t)c * HW];
            x2 += xr[c] * xr[c];
        }
        const int rb = tid * WPAD;
        #pragma unroll
        for (int w0 = 0; w0 < 32; w0++) {
            const int w = (w0 + tid) & 31;       // rotate: write bank = 5*lane
            float v0 = xr[2 * w], v1 = xr[2 * w + 1];
            __half h0 = __float2half_rn(v0), h1 = __float2half_rn(v1);
            __half l0 = __float2half_rn(v0 - __half2float(h0));
            __half l1 = __float2half_rn(v1 - __half2float(h1));
            xsu[rb + w]      = pack_h2(h0, h1);
            xsu[rb + 32 + w] = pack_h2(l0, l1);
        }
    }

    // ---- stage codebook split planes (warp-cooperative, conflict-free) ----
    for (int c = wid; c < KCODE; c += 8) {
        const float2 v = ((const float2*)(emb + c * CDIM))[lane];  // el 2l,2l+1
        __half h0 = __float2half_rn(v.x), h1 = __float2half_rn(v.y);
        __half l0 = __float2half_rn(v.x - __half2float(h0));
        __half l1 = __float2half_rn(v.y - __half2float(h1));
        esu[c * WPAD + lane]      = pack_h2(h0, h1);
        esu[c * WPAD + 32 + lane] = pack_h2(l0, l1);
    }

    // ---- e2 from global + hist init ----
    #pragma unroll
    for (int i = tid; i < KCODE; i += TPB) {
        const float4* e4 = (const float4*)(emb + i * CDIM);
        float s = 0.f;
        #pragma unroll
        for (int j = 0; j < CDIM / 4; j++) {
            float4 e = e4[j];
            s += e.x * e.x + e.y * e.y + e.z * e.z + e.w * e.w;
        }
        e2s[i] = s;
        s_hist[i] = 0;
    }
    __syncthreads();

    // ---- mma GEMM: 64-code chunks, fp16 3-split, k16 steps ----
    float best[4] = {3.402823e38f, 3.402823e38f, 3.402823e38f, 3.402823e38f};
    int   bidx[4] = {0, 0, 0, 0};

    for (int cb = 0; cb < KCODE; cb += 64) {
        float acc[2][8][4];
        #pragma unroll
        for (int mt = 0; mt < 2; mt++)
            #pragma unroll
            for (int nt = 0; nt < 8; nt++)
                #pragma unroll
                for (int r = 0; r < 4; r++) acc[mt][nt][r] = 0.f;

        #pragma unroll
        for (int ks = 0; ks < 4; ks++) {        // K = 4 x 16
            const int wb = 8 * ks + lc;          // hi word base for this lane

            // A fragments (hi/lo), both 16-row tiles
            uint32_t ah[2][4], al[2][4];
            #pragma unroll
            for (int mt = 0; mt < 2; mt++) {
                const int r0 = (mbase + mt * 16 + lr) * WPAD;
                const int r1 = r0 + 8 * WPAD;
                ah[mt][0] = xsu[r0 + wb];          ah[mt][1] = xsu[r1 + wb];
                ah[mt][2] = xsu[r0 + wb + 4];      ah[mt][3] = xsu[r1 + wb + 4];
                al[mt][0] = xsu[r0 + 32 + wb];     al[mt][1] = xsu[r1 + 32 + wb];
                al[mt][2] = xsu[r0 + 32 + wb + 4]; al[mt][3] = xsu[r1 + 32 + wb + 4];
            }

            // B fragments (hi/lo) for all 8 n-tiles
            uint32_t bh[8][2], bl[8][2];
            #pragma unroll
            for (int nt = 0; nt < 8; nt++) {
                const int c0 = (cb + nt * 8 + lr) * WPAD;
                bh[nt][0] = esu[c0 + wb];      bh[nt][1] = esu[c0 + wb + 4];
                bl[nt][0] = esu[c0 + 32 + wb]; bl[nt][1] = esu[c0 + 32 + wb + 4];
            }

            // Three passes over 16 distinct accumulators (RAW-safe anyway)
            #pragma unroll
            for (int nt = 0; nt < 8; nt++) {        // hi * hi
                mma_f16(acc[0][nt], ah[0], bh[nt][0], bh[nt][1]);
                mma_f16(acc[1][nt], ah[1], bh[nt][0], bh[nt][1]);
            }
            #pragma unroll
            for (int nt = 0; nt < 8; nt++) {        // hi * lo
                mma_f16(acc[0][nt], ah[0], bl[nt][0], bl[nt][1]);
                mma_f16(acc[1][nt], ah[1], bl[nt][0], bl[nt][1]);
            }
            #pragma unroll
            for (int nt = 0; nt < 8; nt++) {        // lo * hi
                mma_f16(acc[0][nt], al[0], bh[nt][0], bh[nt][1]);
                mma_f16(acc[1][nt], al[1], bh[nt][0], bh[nt][1]);
            }
        }

        // chunk epilogue: d = e2 - 2*dot, running argmin (cols ascending)
        #pragma unroll
        for (int nt = 0; nt < 8; nt++) {
            const int col0 = cb + nt * 8 + lc * 2;
            const float e20 = e2s[col0];
            const float e21 = e2s[col0 + 1];
            #pragma unroll
            for (int mt = 0; mt < 2; mt++) {
                #pragma unroll
                for (int h = 0; h < 2; h++) {     // h=0: row lr, h=1: row lr+8
                    const int slot = mt * 2 + h;
                    float d0 = fmaf(-2.f, acc[mt][nt][2*h    ], e20);
                    float d1 = fmaf(-2.f, acc[mt][nt][2*h + 1], e21);
                    if (d0 < best[slot]) { best[slot] = d0; bidx[slot] = col0; }
                    if (d1 < best[slot]) { best[slot] = d1; bidx[slot] = col0 + 1; }
                }
            }
        }
    }

    // ---- reduce across the 4 lanes of each row-quad (tie -> lower idx) ----
    #pragma unroll
    for (int s = 0; s < 4; s++) {
        #pragma unroll
        for (int off = 1; off <= 2; off <<= 1) {
            float ov = __shfl_xor_sync(0xFFFFFFFFu, best[s], off);
            int   oi = __shfl_xor_sync(0xFFFFFFFFu, bidx[s], off);
            if (ov < best[s] || (ov == best[s] && oi < bidx[s])) {
                best[s] = ov; bidx[s] = oi;
            }
        }
    }
    if (lc == 0) {
        #pragma unroll
        for (int s = 0; s < 4; s++) {
            const int row = mbase + ((s & 1) << 3) + ((s >> 1) << 4) + lr;
            s_best[row] = best[s];
            s_bidx[row] = bidx[s];
        }
    }
    __syncthreads();

    // ---- per-row epilogue (row = tid) ----
    const int   kbest = s_bidx[tid];
    const float dbest = s_best[tid];

    atomicAdd(&s_hist[kbest], 1);
    out[IDX_OFF + n] = (float)kbest;

    {   // scatter exact fp32 code row from global (codebook is L2-hot)
        float* op = out + (size_t)b * CDIM * HW + hw;
        const float4* eb = (const float4*)(emb + kbest * CDIM);
        #pragma unroll
        for (int j = 0; j < CDIM / 4; j++) {
            float4 e = eb[j];
            op[(size_t)(4 * j + 0) * HW] = e.x;
            op[(size_t)(4 * j + 1) * HW] = e.y;
            op[(size_t)(4 * j + 2) * HW] = e.z;
            op[(size_t)(4 * j + 3) * HW] = e.w;
        }
    }

    // commitment partial: ||x - e||^2 = x2 + (e2 - 2 dot)
    float dsum = x2 + dbest;
    #pragma unroll
    for (int off = 16; off > 0; off >>= 1)
        dsum += __shfl_down_sync(0xFFFFFFFFu, dsum, off);
    if (lane == 0) s_red[wid] = dsum;
    __syncthreads();
    if (tid == 0) {
        float t = 0.f;
        #pragma unroll
        for (int w = 0; w < TPB / 32; w++) t += s_red[w];
        g_partial[blockIdx.x] = t;
    }
    for (int i = tid; i < KCODE; i += TPB) {
        int h = s_hist[i];
        if (h) atomicAdd(&g_hist[i], h);
    }
}

// ---------------------------------------------------------------------------
// Kernel 2: finalize scalars (re-zeroes g_hist for the next graph replay)
// ---------------------------------------------------------------------------
__global__ void vq_finalize(const float* __restrict__ weight,
                            float* __restrict__ out) {
    __shared__ float red[KCODE];
    const int t = threadIdx.x;  // 512

    int   hcount = g_hist[t];
    g_hist[t] = 0;
    float p = (float)hcount * (1.0f / (float)NROWS);
    red[t] = p * logf(p + 1e-10f);
    __syncthreads();
    #pragma unroll
    for (int s = KCODE / 2; s > 0; s >>= 1) {
        if (t < s) red[t] += red[t + s];
        __syncthreads();
    }
    float ent = red[0];
    __syncthreads();

    red[t] = (t < NBLK) ? g_partial[t] : 0.f;
    __syncthreads();
    #pragma unroll
    for (int s = KCODE / 2; s > 0; s >>= 1) {
        if (t < s) red[t] += red[t + s];
        __syncthreads();
    }
    float csum = red[0];
    __syncthreads();

    red[t] = (weight[t] >= 0.01f) ? 1.f : 0.f;
    __syncthreads();
    #pragma unroll
    for (int s = KCODE / 2; s > 0; s >>= 1) {
        if (t < s) red[t] += red[t + s];
        __syncthreads();
    }

    if (t == 0) {
        out[COMMIT_OFF] = csum * (1.0f / (float)OUT_ELEMS);
        out[PERP_OFF]   = expf(-ent);
        out[ACT_OFF]    = red[0];
    }
}

// ---------------------------------------------------------------------------
extern "C" void kernel_launch(void* const* d_in, const int* in_sizes, int n_in,
                              void* d_out, int out_size) {
    const float* in     = (const float*)d_in[0];
    const float* emb    = (const float*)d_in[1];
    const float* weight = (const float*)d_in[2];
    float*       out    = (float*)d_out;

    cudaFuncSetAttribute(vq_main, cudaFuncAttributeMaxDynamicSharedMemorySize,
                         SMEM_BYTES);

    vq_main<<<NBLK, TPB, SMEM_BYTES>>>(in, emb, out);
    vq_finalize<<<1, KCODE>>>(weight, out);
}